// round 1
// baseline (speedup 1.0000x reference)
#include <cuda_runtime.h>
#include <math.h>

// ---------------------------------------------------------------------------
// CorrLayerDownsample: only 7 correlation lags per (j1,j2,l1,l2) survive.
//   same scale :  corr[u] = sum_q x1[(u+q) mod] * x2[q]
//   cross scale:  corr[u] = sum_{q coarse} x2[q] * Z1[(u + r q) mod]
//     Z1 = Re{ band-limited x1 }, band nu in [-m/2, m/2) (asymmetric Nyquist),
//     separable complex Dirichlet kernel phi_{m,h}(t) = (1/m) sum_nu e^{2pi i nu t/h}
// Output [2, 6*64, 7]; shift order (sorted union flat idx, same at all scales):
//   (0,0),(0,1),(0,2),(1,0),(1,1),(2,0),(-1,1)
// ---------------------------------------------------------------------------

#define LCH 8

__device__ float2 g_phi01[256];          // m=128, h=256
__device__ float2 g_phi02[256];          // m=64,  h=256
__device__ float2 g_phi12[128];          // m=64,  h=128
__device__ float2 g_W[16 * 256 * 256];   // row-conv scratch (reused per combo)
__device__ float  g_Z01[16 * 256 * 256];
__device__ float  g_Z02[16 * 256 * 256];
__device__ float  g_Z12[16 * 128 * 128];

__constant__ int c_dx[7] = {0, 0, 0, 1, 1, 2, -1};
__constant__ int c_dy[7] = {0, 1, 2, 0, 1, 0, 1};

// Exact Dirichlet kernel by direct double summation (handles the asymmetric
// band / Nyquist exactly; 82K trig ops total -> negligible).
__global__ void init_phi_kernel() {
    int c = blockIdx.x;
    int t = threadIdx.x;
    int m = (c == 0) ? 128 : 64;
    int h = (c == 2) ? 128 : 256;
    if (t >= h) return;
    double re = 0.0, im = 0.0;
    for (int v = -m / 2; v < m / 2; ++v) {
        double ang = 6.283185307179586476925286766559 * (double)(v * t) / (double)h;
        re += cos(ang);
        im += sin(ang);
    }
    float2 val = make_float2((float)(re / (double)m), (float)(im / (double)m));
    if (c == 0)      g_phi01[t] = val;
    else if (c == 1) g_phi02[t] = val;
    else             g_phi12[t] = val;
}

// Pass 1: row-wise circular conv (along y): W[img][px][ty] = sum_py x * phi(ty-py)
// R rows per block so the phi shared-load amortizes across rows.
template <int H, int R>
__global__ void __launch_bounds__(H) pass1_kernel(const float* __restrict__ x,
                                                  float2* __restrict__ W,
                                                  const float2* __restrict__ phi) {
    __shared__ float  xs[R * H];
    __shared__ float2 ps[H];
    int img = blockIdx.y;
    int px0 = blockIdx.x * R;
    int ty  = threadIdx.x;
    const float* base = x + ((size_t)img * H + px0) * H;
    ps[ty] = phi[ty];
#pragma unroll
    for (int rr = 0; rr < R; ++rr) xs[rr * H + ty] = base[rr * H + ty];
    __syncthreads();
    float ar[R], ai[R];
#pragma unroll
    for (int rr = 0; rr < R; ++rr) { ar[rr] = 0.f; ai[rr] = 0.f; }
#pragma unroll 4
    for (int py = 0; py < H; ++py) {
        float2 p = ps[(ty - py) & (H - 1)];
#pragma unroll
        for (int rr = 0; rr < R; ++rr) {
            float v = xs[rr * H + py];   // broadcast
            ar[rr] += v * p.x;
            ai[rr] += v * p.y;
        }
    }
    float2* wb = W + ((size_t)img * H + px0) * H + ty;
#pragma unroll
    for (int rr = 0; rr < R; ++rr) wb[(size_t)rr * H] = make_float2(ar[rr], ai[rr]);
}

// Pass 2: column-wise conv + take real:
// Z[tx][ty] = sum_px (Wr*phiR(tx-px) - Wi*phiI(tx-px)); TX tx outputs / thread
template <int H, int TX>
__global__ void __launch_bounds__(H) pass2_kernel(const float2* __restrict__ W,
                                                  float* __restrict__ Z,
                                                  const float2* __restrict__ phi) {
    __shared__ float2 ps[H];
    int img = blockIdx.y;
    int tx0 = blockIdx.x * TX;
    int ty  = threadIdx.x;
    ps[ty] = phi[ty];
    __syncthreads();
    float acc[TX];
#pragma unroll
    for (int i = 0; i < TX; ++i) acc[i] = 0.f;
    const float2* Wb = W + (size_t)img * H * H;
    for (int px = 0; px < H; ++px) {
        float2 wv = Wb[(size_t)px * H + ty];
        int bi = (tx0 - px) & (H - 1);
#pragma unroll
        for (int i = 0; i < TX; ++i) {
            float2 p = ps[(bi + i) & (H - 1)];   // broadcast
            acc[i] += wv.x * p.x - wv.y * p.y;
        }
    }
    float* zb = Z + (size_t)img * H * H + (size_t)tx0 * H + ty;
#pragma unroll
    for (int i = 0; i < TX; ++i) zb[(size_t)i * H] = acc[i];
}

// Generic correlation: for one pair, shift s, batch b, q-chunk:
//   acc[l1*8+l2] += A[b,l1, (dx + r qx) mod h, (dy + r qy) mod h] * B[b,l2,qx,qy]
// (same-scale pairs: A = B = x_j, r=1).
__global__ void __launch_bounds__(256) corr_kernel(const float* __restrict__ A,
                                                   const float* __restrict__ B,
                                                   float* __restrict__ out,
                                                   int r, int m, int h, int lm,
                                                   int qchunk, int pairBase) {
    int b = blockIdx.z;
    int s = blockIdx.y;
    int dx = c_dx[s], dy = c_dy[s];
    const float* Ab = A + (size_t)b * LCH * h * h;
    const float* Bb = B + (size_t)b * LCH * m * m;
    int hh = h * h, mm = m * m;
    int q0 = blockIdx.x * qchunk;
    float acc[64];
#pragma unroll
    for (int k = 0; k < 64; ++k) acc[k] = 0.f;
    for (int q = q0 + threadIdx.x; q < q0 + qchunk; q += 256) {
        int qx = q >> lm;
        int qy = q & (m - 1);
        int fx = dx + r * qx;
        if (fx < 0)  fx += h;
        if (fx >= h) fx -= h;
        int fy = dy + r * qy;
        if (fy >= h) fy -= h;
        int fo = fx * h + fy;
        float a[8], c[8];
#pragma unroll
        for (int l = 0; l < 8; ++l) a[l] = Ab[(size_t)l * hh + fo];
#pragma unroll
        for (int l = 0; l < 8; ++l) c[l] = Bb[(size_t)l * mm + q];
#pragma unroll
        for (int i = 0; i < 8; ++i)
#pragma unroll
            for (int j = 0; j < 8; ++j) acc[i * 8 + j] = fmaf(a[i], c[j], acc[i * 8 + j]);
    }
    __shared__ float red[64 * 8];
    int lane = threadIdx.x & 31;
    int wid  = threadIdx.x >> 5;
#pragma unroll
    for (int k = 0; k < 64; ++k) {
        float v = acc[k];
        v += __shfl_down_sync(0xffffffffu, v, 16);
        v += __shfl_down_sync(0xffffffffu, v, 8);
        v += __shfl_down_sync(0xffffffffu, v, 4);
        v += __shfl_down_sync(0xffffffffu, v, 2);
        v += __shfl_down_sync(0xffffffffu, v, 1);
        if (lane == 0) red[k * 8 + wid] = v;
    }
    __syncthreads();
    if (threadIdx.x < 64) {
        float sum = 0.f;
#pragma unroll
        for (int w8 = 0; w8 < 8; ++w8) sum += red[threadIdx.x * 8 + w8];
        // out[b][pairBase + l1*8 + l2][s], 384 pairs * 7 shifts per batch
        atomicAdd(&out[(size_t)b * 2688 + (size_t)(pairBase + threadIdx.x) * 7 + s], sum);
    }
}

extern "C" void kernel_launch(void* const* d_in, const int* in_sizes, int n_in,
                              void* d_out, int out_size) {
    const float* x0 = nullptr;
    const float* x1 = nullptr;
    const float* x2 = nullptr;
    for (int i = 0; i < n_in; ++i) {
        if (in_sizes[i] == 2 * 8 * 256 * 256)      x0 = (const float*)d_in[i];
        else if (in_sizes[i] == 2 * 8 * 128 * 128) x1 = (const float*)d_in[i];
        else if (in_sizes[i] == 2 * 8 * 64 * 64)   x2 = (const float*)d_in[i];
    }
    float* out = (float*)d_out;

    float2 *phi01, *phi02, *phi12, *W;
    float *Z01, *Z02, *Z12;
    cudaGetSymbolAddress((void**)&phi01, g_phi01);
    cudaGetSymbolAddress((void**)&phi02, g_phi02);
    cudaGetSymbolAddress((void**)&phi12, g_phi12);
    cudaGetSymbolAddress((void**)&W,     g_W);
    cudaGetSymbolAddress((void**)&Z01,   g_Z01);
    cudaGetSymbolAddress((void**)&Z02,   g_Z02);
    cudaGetSymbolAddress((void**)&Z12,   g_Z12);

    cudaMemsetAsync(d_out, 0, (size_t)out_size * sizeof(float));
    init_phi_kernel<<<3, 256>>>();

    // Band-limited images (cross-scale pairs). g_W is reused; stream-serialized.
    pass1_kernel<256, 8><<<dim3(32, 16), 256>>>(x0, W, phi01);
    pass2_kernel<256, 16><<<dim3(16, 16), 256>>>(W, Z01, phi01);

    pass1_kernel<256, 8><<<dim3(32, 16), 256>>>(x0, W, phi02);
    pass2_kernel<256, 16><<<dim3(16, 16), 256>>>(W, Z02, phi02);

    pass1_kernel<128, 8><<<dim3(16, 16), 128>>>(x1, W, phi12);
    pass2_kernel<128, 16><<<dim3(8, 16), 128>>>(W, Z12, phi12);

    // Correlations: grid = (q-chunks, 7 shifts, 2 batches)
    // pair (0,0)
    corr_kernel<<<dim3(16, 7, 2), 256>>>(x0,  x0, out, 1, 256, 256, 8, 4096, 0);
    // pair (0,1)
    corr_kernel<<<dim3(4, 7, 2), 256>>>(Z01, x1, out, 2, 128, 256, 7, 4096, 64);
    // pair (0,2)
    corr_kernel<<<dim3(1, 7, 2), 256>>>(Z02, x2, out, 4, 64, 256, 6, 4096, 128);
    // pair (1,1)
    corr_kernel<<<dim3(4, 7, 2), 256>>>(x1,  x1, out, 1, 128, 128, 7, 4096, 192);
    // pair (1,2)
    corr_kernel<<<dim3(1, 7, 2), 256>>>(Z12, x2, out, 2, 64, 128, 6, 4096, 256);
    // pair (2,2)
    corr_kernel<<<dim3(1, 7, 2), 256>>>(x2,  x2, out, 1, 64, 64, 6, 4096, 320);
}

// round 2
// speedup vs baseline: 4.0175x; 4.0175x over previous
#include <cuda_runtime.h>
#include <math.h>

// ---------------------------------------------------------------------------
// CorrLayerDownsample: only 7 correlation lags per (j1,j2,l1,l2) survive.
//   same scale :  corr[u] = sum_q x1[(u+q) mod] * x2[q]
//   cross scale:  corr[u] = sum_{q coarse} x2[q] * Z1[(u + r q) mod]
//     Z1 = Re{ band-limited x1 }, band nu in [-m/2, m/2) (asymmetric Nyquist),
//     separable Dirichlet kernel phi_{m,h}(t) = (1/m) sum_nu e^{2pi i nu t/h}
//                              = (1/m) e^{-i w/2} sin(m w/2)/sin(w/2), w=2pi t/h
// Output [2, 6*64, 7]; shift order (sorted union flat idx, same at all scales):
//   (0,0),(0,1),(0,2),(1,0),(1,1),(2,0),(-1,1)
// ---------------------------------------------------------------------------

#define LCH 8

__device__ float2 g_phi01[256];          // m=128, h=256
__device__ float2 g_phi02[256];          // m=64,  h=256
__device__ float2 g_phi12[128];          // m=64,  h=128
__device__ float2 g_W01[16 * 256 * 256];
__device__ float2 g_W02[16 * 256 * 256];
__device__ float2 g_W12[16 * 128 * 128];
__device__ float  g_Z01[16 * 256 * 256];
__device__ float  g_Z02[16 * 256 * 256];
__device__ float  g_Z12[16 * 128 * 128];

__constant__ int c_dx[7] = {0, 0, 0, 1, 1, 2, -1};
__constant__ int c_dy[7] = {0, 1, 2, 0, 1, 0, 1};

// Closed-form Dirichlet kernel: 3 double trig calls per element (was 256 —
// that DP-trig loop cost ~1.2 ms on its own).
__global__ void init_phi_kernel() {
    int c = blockIdx.x;
    int t = threadIdx.x;
    int m = (c == 0) ? 128 : 64;
    int h = (c == 2) ? 128 : 256;
    if (t >= h) return;
    float2 val;
    if (t == 0) {
        val = make_float2(1.f, 0.f);
    } else {
        double wh = 3.1415926535897932384626433832795 * (double)t / (double)h; // w/2
        double s  = sin((double)m * wh) / sin(wh);
        val = make_float2((float)(cos(wh) * s / (double)m),
                          (float)(-sin(wh) * s / (double)m));
    }
    if (c == 0)      g_phi01[t] = val;
    else if (c == 1) g_phi02[t] = val;
    else             g_phi12[t] = val;
}

// Pass 1: row-wise circular conv (along y): W[img][px][ty] = sum_py x * phi(ty-py)
// R rows per block; py unrolled by 4 with float4 broadcast shared loads.
template <int H, int R>
__global__ void __launch_bounds__(H) pass1_kernel(const float* __restrict__ x,
                                                  float2* __restrict__ W,
                                                  const float2* __restrict__ phi) {
    __shared__ float  xs[R * H];
    __shared__ float2 ps[H];
    int img = blockIdx.y;
    int px0 = blockIdx.x * R;
    int ty  = threadIdx.x;
    const float* base = x + ((size_t)img * H + px0) * H;
    ps[ty] = phi[ty];
#pragma unroll
    for (int rr = 0; rr < R; ++rr) xs[rr * H + ty] = base[rr * H + ty];
    __syncthreads();
    float ar[R], ai[R];
#pragma unroll
    for (int rr = 0; rr < R; ++rr) { ar[rr] = 0.f; ai[rr] = 0.f; }
    for (int py = 0; py < H; py += 4) {
        float2 p0 = ps[(ty - py)     & (H - 1)];
        float2 p1 = ps[(ty - py - 1) & (H - 1)];
        float2 p2 = ps[(ty - py - 2) & (H - 1)];
        float2 p3 = ps[(ty - py - 3) & (H - 1)];
#pragma unroll
        for (int rr = 0; rr < R; ++rr) {
            float4 v = *(const float4*)&xs[rr * H + py];   // broadcast LDS.128
            ar[rr] += v.x * p0.x + v.y * p1.x + v.z * p2.x + v.w * p3.x;
            ai[rr] += v.x * p0.y + v.y * p1.y + v.z * p2.y + v.w * p3.y;
        }
    }
    float2* wb = W + ((size_t)img * H + px0) * H + ty;
#pragma unroll
    for (int rr = 0; rr < R; ++rr) wb[(size_t)rr * H] = make_float2(ar[rr], ai[rr]);
}

// Pass 2: column-wise conv + take real:
// Z[tx][ty] = sum_px (Wr*phiR(tx-px) - Wi*phiI(tx-px)); TX tx outputs / thread.
// phi duplicated to 2H so the TX-tap window is contiguous (no mod per tap).
template <int H, int TX>
__global__ void __launch_bounds__(H) pass2_kernel(const float2* __restrict__ W,
                                                  float* __restrict__ Z,
                                                  const float2* __restrict__ phi) {
    __shared__ float2 ps[2 * H];
    int img = blockIdx.y;
    int tx0 = blockIdx.x * TX;
    int ty  = threadIdx.x;
    float2 pv = phi[ty];
    ps[ty] = pv;
    ps[ty + H] = pv;
    __syncthreads();
    float acc[TX];
#pragma unroll
    for (int i = 0; i < TX; ++i) acc[i] = 0.f;
    const float2* Wb = W + (size_t)img * H * H;
    for (int px = 0; px < H; ++px) {
        float2 wv = Wb[(size_t)px * H + ty];
        int bi = tx0 - px;
        if (bi < 0) bi += H;            // bi in [0, H)
#pragma unroll
        for (int i = 0; i < TX; ++i) {
            float2 p = ps[bi + i];      // contiguous, broadcast
            acc[i] += wv.x * p.x - wv.y * p.y;
        }
    }
    float* zb = Z + (size_t)img * H * H + (size_t)tx0 * H + ty;
#pragma unroll
    for (int i = 0; i < TX; ++i) zb[(size_t)i * H] = acc[i];
}

// Generic correlation: for one pair, shift s, batch b, q-chunk:
//   acc[l1*8+l2] += A[b,l1, (dx + r qx) mod h, (dy + r qy) mod h] * B[b,l2,qx,qy]
__global__ void __launch_bounds__(256) corr_kernel(const float* __restrict__ A,
                                                   const float* __restrict__ B,
                                                   float* __restrict__ out,
                                                   int r, int m, int h, int lm,
                                                   int qchunk, int pairBase) {
    int b = blockIdx.z;
    int s = blockIdx.y;
    int dx = c_dx[s], dy = c_dy[s];
    const float* Ab = A + (size_t)b * LCH * h * h;
    const float* Bb = B + (size_t)b * LCH * m * m;
    int hh = h * h, mm = m * m;
    int q0 = blockIdx.x * qchunk;
    float acc[64];
#pragma unroll
    for (int k = 0; k < 64; ++k) acc[k] = 0.f;
    for (int q = q0 + threadIdx.x; q < q0 + qchunk; q += 256) {
        int qx = q >> lm;
        int qy = q & (m - 1);
        int fx = dx + r * qx;
        if (fx < 0)  fx += h;
        if (fx >= h) fx -= h;
        int fy = dy + r * qy;
        if (fy >= h) fy -= h;
        int fo = fx * h + fy;
        float a[8], c[8];
#pragma unroll
        for (int l = 0; l < 8; ++l) a[l] = Ab[(size_t)l * hh + fo];
#pragma unroll
        for (int l = 0; l < 8; ++l) c[l] = Bb[(size_t)l * mm + q];
#pragma unroll
        for (int i = 0; i < 8; ++i)
#pragma unroll
            for (int j = 0; j < 8; ++j) acc[i * 8 + j] = fmaf(a[i], c[j], acc[i * 8 + j]);
    }
    __shared__ float red[64 * 8];
    int lane = threadIdx.x & 31;
    int wid  = threadIdx.x >> 5;
#pragma unroll
    for (int k = 0; k < 64; ++k) {
        float v = acc[k];
        v += __shfl_down_sync(0xffffffffu, v, 16);
        v += __shfl_down_sync(0xffffffffu, v, 8);
        v += __shfl_down_sync(0xffffffffu, v, 4);
        v += __shfl_down_sync(0xffffffffu, v, 2);
        v += __shfl_down_sync(0xffffffffu, v, 1);
        if (lane == 0) red[k * 8 + wid] = v;
    }
    __syncthreads();
    if (threadIdx.x < 64) {
        float sum = 0.f;
#pragma unroll
        for (int w8 = 0; w8 < 8; ++w8) sum += red[threadIdx.x * 8 + w8];
        atomicAdd(&out[(size_t)b * 2688 + (size_t)(pairBase + threadIdx.x) * 7 + s], sum);
    }
}

extern "C" void kernel_launch(void* const* d_in, const int* in_sizes, int n_in,
                              void* d_out, int out_size) {
    const float* x0 = nullptr;
    const float* x1 = nullptr;
    const float* x2 = nullptr;
    for (int i = 0; i < n_in; ++i) {
        if (in_sizes[i] == 2 * 8 * 256 * 256)      x0 = (const float*)d_in[i];
        else if (in_sizes[i] == 2 * 8 * 128 * 128) x1 = (const float*)d_in[i];
        else if (in_sizes[i] == 2 * 8 * 64 * 64)   x2 = (const float*)d_in[i];
    }
    float* out = (float*)d_out;

    float2 *phi01, *phi02, *phi12, *W01, *W02, *W12;
    float *Z01, *Z02, *Z12;
    cudaGetSymbolAddress((void**)&phi01, g_phi01);
    cudaGetSymbolAddress((void**)&phi02, g_phi02);
    cudaGetSymbolAddress((void**)&phi12, g_phi12);
    cudaGetSymbolAddress((void**)&W01,   g_W01);
    cudaGetSymbolAddress((void**)&W02,   g_W02);
    cudaGetSymbolAddress((void**)&W12,   g_W12);
    cudaGetSymbolAddress((void**)&Z01,   g_Z01);
    cudaGetSymbolAddress((void**)&Z02,   g_Z02);
    cudaGetSymbolAddress((void**)&Z12,   g_Z12);

    cudaMemsetAsync(d_out, 0, (size_t)out_size * sizeof(float));
    init_phi_kernel<<<3, 256>>>();

    // Band-limited images for cross-scale pairs.
    pass1_kernel<256, 16><<<dim3(16, 16), 256>>>(x0, W01, phi01);
    pass2_kernel<256, 16><<<dim3(16, 16), 256>>>(W01, Z01, phi01);

    pass1_kernel<256, 16><<<dim3(16, 16), 256>>>(x0, W02, phi02);
    pass2_kernel<256, 16><<<dim3(16, 16), 256>>>(W02, Z02, phi02);

    pass1_kernel<128, 16><<<dim3(8, 16), 128>>>(x1, W12, phi12);
    pass2_kernel<128, 16><<<dim3(8, 16), 128>>>(W12, Z12, phi12);

    // Correlations: grid = (q-chunks, 7 shifts, 2 batches)
    corr_kernel<<<dim3(16, 7, 2), 256>>>(x0,  x0, out, 1, 256, 256, 8, 4096, 0);
    corr_kernel<<<dim3(4, 7, 2), 256>>>(Z01, x1, out, 2, 128, 256, 7, 4096, 64);
    corr_kernel<<<dim3(1, 7, 2), 256>>>(Z02, x2, out, 4, 64, 256, 6, 4096, 128);
    corr_kernel<<<dim3(4, 7, 2), 256>>>(x1,  x1, out, 1, 128, 128, 7, 4096, 192);
    corr_kernel<<<dim3(1, 7, 2), 256>>>(Z12, x2, out, 2, 64, 128, 6, 4096, 256);
    corr_kernel<<<dim3(1, 7, 2), 256>>>(x2,  x2, out, 1, 64, 64, 6, 4096, 320);
}

// round 3
// speedup vs baseline: 11.1434x; 2.7737x over previous
#include <cuda_runtime.h>
#include <math.h>

// ---------------------------------------------------------------------------
// corr[u] = Sum_t x1[t] * Re(u2c[(t-u) mod h]),
//   u2c = separable Dirichlet upsample of the coarser x2:
//   u2c[t] = Sum_q x2[q] phi(t_x - r q_x) phi(t_y - r q_y),
//   phi_{m,h}(t) = (1/m) e^{-i w/2} sin(m w/2)/sin(w/2), w = 2 pi t / h.
// Same scale: phi = delta -> corr[u] = Sum_q x1[q+u] x2[q].
// Output [2, 6*64, 7]; shifts (0,0),(0,1),(0,2),(1,0),(1,1),(2,0),(-1,1).
// ---------------------------------------------------------------------------

#define LCH 8

__device__ float2 g_phi01[256];          // m=128, h=256
__device__ float2 g_phi02[256];          // m=64,  h=256
__device__ float2 g_phi12[128];          // m=64,  h=128
__device__ float2 g_A01[16 * 128 * 256]; // upA scratch (complex)
__device__ float2 g_A02[16 * 64 * 256];
__device__ float2 g_A12[16 * 64 * 128];
__device__ float  g_U01[16 * 256 * 256]; // upsampled x2 (real part)
__device__ float  g_U02[16 * 256 * 256];
__device__ float  g_U12[16 * 128 * 128];

__constant__ int c_dx[7] = {0, 0, 0, 1, 1, 2, -1};
__constant__ int c_dy[7] = {0, 1, 2, 0, 1, 0, 1};
// corr groups: (0,0) (0,1) (0,2) (1,1) (1,2) (2,2); qblocks 16,16,16,4,4,1
__constant__ int c_gstart[7] = {0, 16, 32, 48, 52, 56, 57};
__constant__ int c_lm[6]     = {8, 8, 8, 7, 7, 6};
__constant__ int c_sgn[6]    = {1, -1, -1, 1, -1, 1};
__constant__ int c_trans[6]  = {0, 1, 1, 0, 1, 0};
__constant__ int c_pbase[6]  = {0, 64, 128, 192, 256, 320};

// Closed-form Dirichlet kernel (3 DP trig calls per element).
__global__ void init_phi_kernel() {
    int c = blockIdx.x;
    int t = threadIdx.x;
    int m = (c == 0) ? 128 : 64;
    int h = (c == 2) ? 128 : 256;
    if (t >= h) return;
    float2 val;
    if (t == 0) {
        val = make_float2(1.f, 0.f);
    } else {
        double wh = 3.1415926535897932384626433832795 * (double)t / (double)h;
        double s  = sin((double)m * wh) / sin(wh);
        val = make_float2((float)(cos(wh) * s / (double)m),
                          (float)(-sin(wh) * s / (double)m));
    }
    if (c == 0)      g_phi01[t] = val;
    else if (c == 1) g_phi02[t] = val;
    else             g_phi12[t] = val;
}

// upA: interpolate coarse x2 along y to the fine grid (complex result).
// A[img][qx][ty] = Sum_qy x2[img][qx][qy] * phi((ty - r*qy) mod HH)
template <int MM, int HH, int R, int RSH>
__global__ void __launch_bounds__(HH) upA_kernel(const float* __restrict__ x,
                                                 float2* __restrict__ A,
                                                 const float2* __restrict__ phi) {
    __shared__ float  xs[R * MM];
    __shared__ float2 ps[HH];
    int img  = blockIdx.y;
    int row0 = blockIdx.x * R;
    int ty   = threadIdx.x;
    ps[ty] = phi[ty];
    const float* xb = x + ((size_t)img * MM + row0) * MM;
#pragma unroll
    for (int i = ty; i < R * MM; i += HH) xs[i] = xb[i];
    __syncthreads();
    float ar[R], ai[R];
#pragma unroll
    for (int rr = 0; rr < R; ++rr) { ar[rr] = 0.f; ai[rr] = 0.f; }
    for (int qy = 0; qy < MM; qy += 4) {
        float2 p0 = ps[(ty - ((qy + 0) << RSH)) & (HH - 1)];
        float2 p1 = ps[(ty - ((qy + 1) << RSH)) & (HH - 1)];
        float2 p2 = ps[(ty - ((qy + 2) << RSH)) & (HH - 1)];
        float2 p3 = ps[(ty - ((qy + 3) << RSH)) & (HH - 1)];
#pragma unroll
        for (int rr = 0; rr < R; ++rr) {
            float4 v = *(const float4*)&xs[rr * MM + qy];   // broadcast LDS.128
            ar[rr] += v.x * p0.x + v.y * p1.x + v.z * p2.x + v.w * p3.x;
            ai[rr] += v.x * p0.y + v.y * p1.y + v.z * p2.y + v.w * p3.y;
        }
    }
    float2* Ab = A + ((size_t)img * MM + row0) * HH + ty;
#pragma unroll
    for (int rr = 0; rr < R; ++rr) Ab[(size_t)rr * HH] = make_float2(ar[rr], ai[rr]);
}

// upB: interpolate along x, take real part.
// U[img][tx][ty] = Re Sum_qx A[img][qx][ty] * phi((tx - r*qx) mod HH)
template <int MM, int HH, int TX, int RSH>
__global__ void __launch_bounds__(HH) upB_kernel(const float2* __restrict__ A,
                                                 float* __restrict__ U,
                                                 const float2* __restrict__ phi) {
    __shared__ float2 ps[2 * HH];
    int img = blockIdx.y;
    int tx0 = blockIdx.x * TX;
    int ty  = threadIdx.x;
    float2 pv = phi[ty];
    ps[ty] = pv;
    ps[ty + HH] = pv;
    __syncthreads();
    float acc[TX];
#pragma unroll
    for (int i = 0; i < TX; ++i) acc[i] = 0.f;
    const float2* Ab = A + (size_t)img * MM * HH + ty;
#pragma unroll 2
    for (int qx = 0; qx < MM; ++qx) {
        float2 av = Ab[(size_t)qx * HH];
        float nay = -av.y;
        int bi = (tx0 - (qx << RSH)) & (HH - 1);
#pragma unroll
        for (int i = 0; i < TX; ++i) {
            float2 p = ps[bi + i];       // same addr across block -> broadcast
            acc[i] = fmaf(av.x, p.x, acc[i]);
            acc[i] = fmaf(nay,  p.y, acc[i]);
        }
    }
    float* Ub = U + (size_t)img * HH * HH + (size_t)tx0 * HH + ty;
#pragma unroll
    for (int i = 0; i < TX; ++i) Ub[(size_t)i * HH] = acc[i];
}

// All correlations in one launch. Per group g:
//   acc[i*8+j] += A_g[b, i, (qx+sgn*dx) mod, (qy+sgn*dy) mod] * B_g[b, j, qx, qy]
// cross-scale groups write transposed (j*8+i) since A holds the j2 channels.
__global__ void __launch_bounds__(256) corr_all_kernel(
    const float* __restrict__ U01, const float* __restrict__ U02,
    const float* __restrict__ U12, const float* __restrict__ x0,
    const float* __restrict__ x1,  const float* __restrict__ x2,
    float* __restrict__ out) {
    int g = 0, bx = blockIdx.x;
    while (bx >= c_gstart[g + 1]) ++g;
    int qblk = bx - c_gstart[g];
    const float *A, *B;
    switch (g) {
        case 0: A = x0;  B = x0; break;
        case 1: A = U01; B = x0; break;
        case 2: A = U02; B = x0; break;
        case 3: A = x1;  B = x1; break;
        case 4: A = U12; B = x1; break;
        default: A = x2; B = x2; break;
    }
    int lm = c_lm[g];
    int h  = 1 << lm;
    int hh = h * h;
    int b  = blockIdx.z, s = blockIdx.y;
    int sg = c_sgn[g];
    int dx = sg * c_dx[s], dy = sg * c_dy[s];
    const float* Ab = A + (size_t)b * LCH * hh;
    const float* Bb = B + (size_t)b * LCH * hh;
    int q0 = qblk * 4096;
    float acc[64];
#pragma unroll
    for (int k = 0; k < 64; ++k) acc[k] = 0.f;
    for (int q = q0 + threadIdx.x; q < q0 + 4096; q += 256) {
        int qx = q >> lm;
        int qy = q & (h - 1);
        int fo = (((qx + dx) & (h - 1)) << lm) + ((qy + dy) & (h - 1));
        float a[8], c[8];
#pragma unroll
        for (int l = 0; l < 8; ++l) a[l] = Ab[(size_t)l * hh + fo];
#pragma unroll
        for (int l = 0; l < 8; ++l) c[l] = Bb[(size_t)l * hh + q];
#pragma unroll
        for (int i = 0; i < 8; ++i)
#pragma unroll
            for (int j = 0; j < 8; ++j)
                acc[i * 8 + j] = fmaf(a[i], c[j], acc[i * 8 + j]);
    }
    __shared__ float red[64 * 8];
    int lane = threadIdx.x & 31;
    int wid  = threadIdx.x >> 5;
#pragma unroll
    for (int k = 0; k < 64; ++k) {
        float v = acc[k];
        v += __shfl_down_sync(0xffffffffu, v, 16);
        v += __shfl_down_sync(0xffffffffu, v, 8);
        v += __shfl_down_sync(0xffffffffu, v, 4);
        v += __shfl_down_sync(0xffffffffu, v, 2);
        v += __shfl_down_sync(0xffffffffu, v, 1);
        if (lane == 0) red[k * 8 + wid] = v;
    }
    __syncthreads();
    if (threadIdx.x < 64) {
        float sum = 0.f;
#pragma unroll
        for (int w8 = 0; w8 < 8; ++w8) sum += red[threadIdx.x * 8 + w8];
        int k = threadIdx.x;
        int p = c_trans[g] ? (((k & 7) << 3) | (k >> 3)) : k;
        atomicAdd(&out[(size_t)b * 2688 + (size_t)(c_pbase[g] + p) * 7 + s], sum);
    }
}

extern "C" void kernel_launch(void* const* d_in, const int* in_sizes, int n_in,
                              void* d_out, int out_size) {
    const float* x0 = nullptr;
    const float* x1 = nullptr;
    const float* x2 = nullptr;
    for (int i = 0; i < n_in; ++i) {
        if (in_sizes[i] == 2 * 8 * 256 * 256)      x0 = (const float*)d_in[i];
        else if (in_sizes[i] == 2 * 8 * 128 * 128) x1 = (const float*)d_in[i];
        else if (in_sizes[i] == 2 * 8 * 64 * 64)   x2 = (const float*)d_in[i];
    }
    float* out = (float*)d_out;

    float2 *phi01, *phi02, *phi12, *A01, *A02, *A12;
    float *U01, *U02, *U12;
    cudaGetSymbolAddress((void**)&phi01, g_phi01);
    cudaGetSymbolAddress((void**)&phi02, g_phi02);
    cudaGetSymbolAddress((void**)&phi12, g_phi12);
    cudaGetSymbolAddress((void**)&A01,   g_A01);
    cudaGetSymbolAddress((void**)&A02,   g_A02);
    cudaGetSymbolAddress((void**)&A12,   g_A12);
    cudaGetSymbolAddress((void**)&U01,   g_U01);
    cudaGetSymbolAddress((void**)&U02,   g_U02);
    cudaGetSymbolAddress((void**)&U12,   g_U12);

    cudaMemsetAsync(d_out, 0, (size_t)out_size * sizeof(float));
    init_phi_kernel<<<3, 256>>>();

    // Upsample the coarser member of each cross-scale pair.
    upA_kernel<128, 256, 8, 1><<<dim3(16, 16), 256>>>(x1, A01, phi01);
    upA_kernel<64, 256, 8, 2><<<dim3(8, 16), 256>>>(x2, A02, phi02);
    upA_kernel<64, 128, 8, 1><<<dim3(8, 16), 128>>>(x2, A12, phi12);

    upB_kernel<128, 256, 16, 1><<<dim3(16, 16), 256>>>(A01, U01, phi01);
    upB_kernel<64, 256, 16, 2><<<dim3(16, 16), 256>>>(A02, U02, phi02);
    upB_kernel<64, 128, 16, 1><<<dim3(8, 16), 128>>>(A12, U12, phi12);

    // All 6 pair-groups, 7 shifts, 2 batches in one launch.
    corr_all_kernel<<<dim3(57, 7, 2), 256>>>(U01, U02, U12, x0, x1, x2, out);
}

// round 4
// speedup vs baseline: 13.6820x; 1.2278x over previous
#include <cuda_runtime.h>
#include <math.h>

// ---------------------------------------------------------------------------
// corr[u] = Sum_t x1[t] * Re(U[(t-u) mod h]),  U = separable Dirichlet
// upsample of the coarser x2.  phi_{m,h}(t) = (1/m) e^{-i pi t/h}
// sin(pi t m/h)/sin(pi t/h);  for h = r*m, phi(t)=0 when t%r==0 (t!=0),
// phi(0)=1, and every tap of output t has argument == t (mod r).
// => outputs with t%r==0 are copies; others use compacted tables
//    phi_c[d] = phi(r*d + c) indexed by (t_coarse - q) mod m.
// Output [2, 6*64, 7]; shifts (0,0),(0,1),(0,2),(1,0),(1,1),(2,0),(-1,1).
// ---------------------------------------------------------------------------

#define LCH 8

__device__ float2 g_p01[128];            // phi_{128,256}(2d+1)
__device__ float2 g_p02[192];            // phi_{64,256}(4d+c), c=1..3
__device__ float2 g_p12[64];             // phi_{64,128}(2d+1)
__device__ float2 g_A01[16 * 128 * 256]; // y-upsampled (complex)
__device__ float2 g_A02[16 * 64 * 256];
__device__ float2 g_A12[16 * 64 * 128];
__device__ float  g_U01[16 * 256 * 256]; // fully upsampled (real)
__device__ float  g_U02[16 * 256 * 256];
__device__ float  g_U12[16 * 128 * 128];

__constant__ int c_dx[7] = {0, 0, 0, 1, 1, 2, -1};
__constant__ int c_dy[7] = {0, 1, 2, 0, 1, 0, 1};
__constant__ int c_gstart[7] = {0, 16, 32, 48, 52, 56, 57};
__constant__ int c_lm[6]     = {8, 8, 8, 7, 7, 6};
__constant__ int c_sgn[6]    = {1, -1, -1, 1, -1, 1};
__constant__ int c_trans[6]  = {0, 1, 1, 0, 1, 0};
__constant__ int c_pbase[6]  = {0, 64, 128, 192, 256, 320};

// Compacted nonzero-tap tables (closed form; t never 0 here).
__global__ void init_phi_kernel() {
    int c = blockIdx.x, tid = threadIdx.x;
    int m, h, t;
    float2* dst;
    if (c == 0) { if (tid >= 128) return; m = 128; h = 256; t = 2 * tid + 1; dst = &g_p01[tid]; }
    else if (c == 1) { if (tid >= 192) return; m = 64; h = 256; t = 4 * (tid & 63) + (tid >> 6) + 1; dst = &g_p02[tid]; }
    else { if (tid >= 64) return; m = 64; h = 128; t = 2 * tid + 1; dst = &g_p12[tid]; }
    double wh = 3.1415926535897932384626433832795 * (double)t / (double)h;
    double s  = sin((double)m * wh) / sin(wh);
    *dst = make_float2((float)(cos(wh) * s / (double)m),
                       (float)(-sin(wh) * s / (double)m));
}

// upA, r=2: A[row][2t+1] = sum_qy x[row][qy] * p01[(t-qy) mod MM];
//           A[row][2t]   = (x[row][t], 0).   HT = MM threads, R rows/block.
template <int MM, int R>
__global__ void __launch_bounds__(MM) upA2_kernel(const float* __restrict__ x,
                                                  float2* __restrict__ A,
                                                  const float2* __restrict__ phi) {
    __shared__ __align__(16) float xs[R * MM];
    __shared__ float2 ps[MM];
    int row0 = blockIdx.x * R;
    int t    = threadIdx.x;
    ps[t] = phi[t];
    const float* xb = x + (size_t)row0 * MM;
#pragma unroll
    for (int i = t; i < R * MM; i += MM) xs[i] = xb[i];
    __syncthreads();
    float ar[R], ai[R];
#pragma unroll
    for (int rr = 0; rr < R; ++rr) { ar[rr] = 0.f; ai[rr] = 0.f; }
    for (int qy = 0; qy < MM; qy += 4) {
        float2 p0 = ps[(t - qy)     & (MM - 1)];
        float2 p1 = ps[(t - qy - 1) & (MM - 1)];
        float2 p2 = ps[(t - qy - 2) & (MM - 1)];
        float2 p3 = ps[(t - qy - 3) & (MM - 1)];
#pragma unroll
        for (int rr = 0; rr < R; ++rr) {
            float4 v = *(const float4*)&xs[rr * MM + qy];   // broadcast LDS.128
            ar[rr] += v.x * p0.x + v.y * p1.x + v.z * p2.x + v.w * p3.x;
            ai[rr] += v.x * p0.y + v.y * p1.y + v.z * p2.y + v.w * p3.y;
        }
    }
    float2* Ab = A + (size_t)row0 * (2 * MM);
#pragma unroll
    for (int rr = 0; rr < R; ++rr) {
        Ab[(size_t)rr * (2 * MM) + 2 * t + 1] = make_float2(ar[rr], ai[rr]);
        Ab[(size_t)rr * (2 * MM) + 2 * t]     = make_float2(xs[rr * MM + t], 0.f);
    }
}

// upA, r=4 (combo 02): MM=64, HH=256. Warps 0-5 compute classes c=1..3,
// warps 6-7 write the t%4==0 copies.
template <int R>
__global__ void __launch_bounds__(256) upA4_kernel(const float* __restrict__ x,
                                                   float2* __restrict__ A,
                                                   const float2* __restrict__ phi) {
    __shared__ __align__(16) float xs[R * 64];
    __shared__ float2 ps[192];
    int row0 = blockIdx.x * R;
    int tid  = threadIdx.x;
    if (tid < 192) ps[tid] = phi[tid];
    const float* xb = x + (size_t)row0 * 64;
    for (int i = tid; i < R * 64; i += 256) xs[i] = xb[i];
    __syncthreads();
    float2* Ab = A + (size_t)row0 * 256;
    if (tid < 192) {
        int cls = tid >> 6;          // 0..2 -> c = cls+1
        int u   = tid & 63;
        const float2* pc = ps + cls * 64;
        float ar[R], ai[R];
#pragma unroll
        for (int rr = 0; rr < R; ++rr) { ar[rr] = 0.f; ai[rr] = 0.f; }
        for (int qy = 0; qy < 64; qy += 4) {
            float2 p0 = pc[(u - qy)     & 63];
            float2 p1 = pc[(u - qy - 1) & 63];
            float2 p2 = pc[(u - qy - 2) & 63];
            float2 p3 = pc[(u - qy - 3) & 63];
#pragma unroll
            for (int rr = 0; rr < R; ++rr) {
                float4 v = *(const float4*)&xs[rr * 64 + qy];
                ar[rr] += v.x * p0.x + v.y * p1.x + v.z * p2.x + v.w * p3.x;
                ai[rr] += v.x * p0.y + v.y * p1.y + v.z * p2.y + v.w * p3.y;
            }
        }
        int ty = 4 * u + cls + 1;
#pragma unroll
        for (int rr = 0; rr < R; ++rr)
            Ab[(size_t)rr * 256 + ty] = make_float2(ar[rr], ai[rr]);
    } else {
        int u = tid & 63;
#pragma unroll
        for (int rr = 0; rr < R; ++rr)
            Ab[(size_t)rr * 256 + 4 * u] = make_float2(xs[rr * 64 + u], 0.f);
    }
}

// upB, r=2: U[2(t0+i)+1][ty] = Re sum_qx A[qx][ty] p01[(t0+i-qx) mod MM];
//           U[2qx][ty] = A[qx][ty].x (written from already-loaded values).
template <int MM, int TX>
__global__ void __launch_bounds__(2 * MM) upB2_kernel(const float2* __restrict__ A,
                                                      float* __restrict__ U,
                                                      const float2* __restrict__ phi) {
    const int HH = 2 * MM;
    __shared__ float2 ps[2 * MM];
    int img = blockIdx.y;
    int t0  = blockIdx.x * TX;
    int ty  = threadIdx.x;
    if (ty < MM) { float2 v = phi[ty]; ps[ty] = v; ps[ty + MM] = v; }
    __syncthreads();
    float acc[TX];
#pragma unroll
    for (int i = 0; i < TX; ++i) acc[i] = 0.f;
    const float2* Ab = A + (size_t)img * MM * HH + ty;
    float* Ub = U + (size_t)img * HH * HH;
#pragma unroll 2
    for (int qx = 0; qx < MM; ++qx) {
        float2 av = Ab[(size_t)qx * HH];
        if ((unsigned)(qx - t0) < (unsigned)TX)
            Ub[(size_t)(2 * qx) * HH + ty] = av.x;         // copy row
        float nay = -av.y;
        int k0 = (t0 - qx) & (MM - 1);
#pragma unroll
        for (int i = 0; i < TX; ++i) {
            float2 p = ps[k0 + i];                          // broadcast
            acc[i] = fmaf(av.x, p.x, acc[i]);
            acc[i] = fmaf(nay,  p.y, acc[i]);
        }
    }
#pragma unroll
    for (int i = 0; i < TX; ++i)
        Ub[(size_t)(2 * (t0 + i) + 1) * HH + ty] = acc[i];
}

// upB, r=4 (combo 02): class c=1..3 per block group; class-1 blocks also
// write the tx%4==0 copy rows.
template <int TX>
__global__ void __launch_bounds__(256) upB4_kernel(const float2* __restrict__ A,
                                                   float* __restrict__ U,
                                                   const float2* __restrict__ phi) {
    __shared__ float2 ps[128];
    int img = blockIdx.y;
    int cls = blockIdx.x / (64 / TX);
    int t0  = (blockIdx.x % (64 / TX)) * TX;
    int ty  = threadIdx.x;
    if (ty < 64) { float2 v = phi[cls * 64 + ty]; ps[ty] = v; ps[ty + 64] = v; }
    __syncthreads();
    float acc[TX];
#pragma unroll
    for (int i = 0; i < TX; ++i) acc[i] = 0.f;
    const float2* Ab = A + (size_t)img * 64 * 256 + ty;
    float* Ub = U + (size_t)img * 256 * 256;
#pragma unroll 2
    for (int qx = 0; qx < 64; ++qx) {
        float2 av = Ab[(size_t)qx * 256];
        if (cls == 0 && (unsigned)(qx - t0) < (unsigned)TX)
            Ub[(size_t)(4 * qx) * 256 + ty] = av.x;
        float nay = -av.y;
        int k0 = (t0 - qx) & 63;
#pragma unroll
        for (int i = 0; i < TX; ++i) {
            float2 p = ps[k0 + i];
            acc[i] = fmaf(av.x, p.x, acc[i]);
            acc[i] = fmaf(nay,  p.y, acc[i]);
        }
    }
#pragma unroll
    for (int i = 0; i < TX; ++i)
        Ub[(size_t)(4 * (t0 + i) + cls + 1) * 256 + ty] = acc[i];
}

// All correlations in one launch (unchanged from passing R3 version).
__global__ void __launch_bounds__(256) corr_all_kernel(
    const float* __restrict__ U01, const float* __restrict__ U02,
    const float* __restrict__ U12, const float* __restrict__ x0,
    const float* __restrict__ x1,  const float* __restrict__ x2,
    float* __restrict__ out) {
    int g = 0, bx = blockIdx.x;
    while (bx >= c_gstart[g + 1]) ++g;
    int qblk = bx - c_gstart[g];
    const float *A, *B;
    switch (g) {
        case 0: A = x0;  B = x0; break;
        case 1: A = U01; B = x0; break;
        case 2: A = U02; B = x0; break;
        case 3: A = x1;  B = x1; break;
        case 4: A = U12; B = x1; break;
        default: A = x2; B = x2; break;
    }
    int lm = c_lm[g];
    int h  = 1 << lm;
    int hh = h * h;
    int b  = blockIdx.z, s = blockIdx.y;
    int sg = c_sgn[g];
    int dx = sg * c_dx[s], dy = sg * c_dy[s];
    const float* Ab = A + (size_t)b * LCH * hh;
    const float* Bb = B + (size_t)b * LCH * hh;
    int q0 = qblk * 4096;
    float acc[64];
#pragma unroll
    for (int k = 0; k < 64; ++k) acc[k] = 0.f;
    for (int q = q0 + threadIdx.x; q < q0 + 4096; q += 256) {
        int qx = q >> lm;
        int qy = q & (h - 1);
        int fo = (((qx + dx) & (h - 1)) << lm) + ((qy + dy) & (h - 1));
        float a[8], c[8];
#pragma unroll
        for (int l = 0; l < 8; ++l) a[l] = Ab[(size_t)l * hh + fo];
#pragma unroll
        for (int l = 0; l < 8; ++l) c[l] = Bb[(size_t)l * hh + q];
#pragma unroll
        for (int i = 0; i < 8; ++i)
#pragma unroll
            for (int j = 0; j < 8; ++j)
                acc[i * 8 + j] = fmaf(a[i], c[j], acc[i * 8 + j]);
    }
    __shared__ float red[64 * 8];
    int lane = threadIdx.x & 31;
    int wid  = threadIdx.x >> 5;
#pragma unroll
    for (int k = 0; k < 64; ++k) {
        float v = acc[k];
        v += __shfl_down_sync(0xffffffffu, v, 16);
        v += __shfl_down_sync(0xffffffffu, v, 8);
        v += __shfl_down_sync(0xffffffffu, v, 4);
        v += __shfl_down_sync(0xffffffffu, v, 2);
        v += __shfl_down_sync(0xffffffffu, v, 1);
        if (lane == 0) red[k * 8 + wid] = v;
    }
    __syncthreads();
    if (threadIdx.x < 64) {
        float sum = 0.f;
#pragma unroll
        for (int w8 = 0; w8 < 8; ++w8) sum += red[threadIdx.x * 8 + w8];
        int k = threadIdx.x;
        int p = c_trans[g] ? (((k & 7) << 3) | (k >> 3)) : k;
        atomicAdd(&out[(size_t)b * 2688 + (size_t)(c_pbase[g] + p) * 7 + s], sum);
    }
}

extern "C" void kernel_launch(void* const* d_in, const int* in_sizes, int n_in,
                              void* d_out, int out_size) {
    const float* x0 = nullptr;
    const float* x1 = nullptr;
    const float* x2 = nullptr;
    for (int i = 0; i < n_in; ++i) {
        if (in_sizes[i] == 2 * 8 * 256 * 256)      x0 = (const float*)d_in[i];
        else if (in_sizes[i] == 2 * 8 * 128 * 128) x1 = (const float*)d_in[i];
        else if (in_sizes[i] == 2 * 8 * 64 * 64)   x2 = (const float*)d_in[i];
    }
    float* out = (float*)d_out;

    float2 *p01, *p02, *p12, *A01, *A02, *A12;
    float *U01, *U02, *U12;
    cudaGetSymbolAddress((void**)&p01, g_p01);
    cudaGetSymbolAddress((void**)&p02, g_p02);
    cudaGetSymbolAddress((void**)&p12, g_p12);
    cudaGetSymbolAddress((void**)&A01, g_A01);
    cudaGetSymbolAddress((void**)&A02, g_A02);
    cudaGetSymbolAddress((void**)&A12, g_A12);
    cudaGetSymbolAddress((void**)&U01, g_U01);
    cudaGetSymbolAddress((void**)&U02, g_U02);
    cudaGetSymbolAddress((void**)&U12, g_U12);

    cudaMemsetAsync(d_out, 0, (size_t)out_size * sizeof(float));
    init_phi_kernel<<<3, 256>>>();

    // y-upsample (odd/residue outputs only; copies folded in)
    upA2_kernel<128, 8><<<256, 128>>>(x1, A01, p01);   // 16*128 rows / 8
    upA4_kernel<8><<<128, 256>>>(x2, A02, p02);        // 16*64 rows / 8
    upA2_kernel<64, 8><<<128, 64>>>(x2, A12, p12);

    // x-upsample + Re (odd/residue rows only; copy rows folded in)
    upB2_kernel<128, 8><<<dim3(16, 16), 256>>>(A01, U01, p01);
    upB4_kernel<8><<<dim3(24, 16), 256>>>(A02, U02, p02);
    upB2_kernel<64, 8><<<dim3(8, 16), 128>>>(A12, U12, p12);

    corr_all_kernel<<<dim3(57, 7, 2), 256>>>(U01, U02, U12, x0, x1, x2, out);
}